// round 13
// baseline (speedup 1.0000x reference)
#include <cuda_runtime.h>

#define BS 2
#define NB 6300
#define NA 85
#define NC 80
#define TOT  (BS * NB)
#define NCLS (BS * NC)

#define CONF_T  0.5f
#define NMS_T   0.4f
#define SCORE_T 0.3f

#define SMAX 256             // mid-path capacity
#define WMAX 8               // mask words per row at SMAX

// -------- device scratch (static allocation; zero-initialized) --------
__device__ int    g_cnt[NCLS];           // self-reset in nms each run
__device__ int    g_lidx[NCLS * NB];     // per-class lists: global box idx
__device__ float  g_lkey[NCLS * NB];     //   objectness (sort key)
__device__ float  g_lms [NCLS * NB];     //   max class score
__device__ float4 g_lbox[NCLS * NB];     //   corners
__device__ int    g_srt [NCLS * NB];     // fallback path only

// ================= kernel 1: prep — 4 boxes per warp =================
__global__ __launch_bounds__(256) void prep_kernel(const float* __restrict__ x,
                                                   float* __restrict__ out) {
    const int warp = (blockIdx.x * blockDim.x + threadIdx.x) >> 5;
    const int lane = threadIdx.x & 31;
    const int g0   = warp * 4;

    // issue all loads for 4 boxes up front (12 independent LDGs in flight)
    float v0[4], v1[4], v2[4];
    #pragma unroll
    for (int b = 0; b < 4; b++) {
        int gi = g0 + b;
        if (gi < TOT) {
            const float* p = x + (size_t)gi * NA;
            v0[b] = p[lane];                           // attrs 0..31
            v1[b] = p[lane + 32];                      // attrs 32..63
            v2[b] = (lane < 21) ? p[lane + 64] : 0.f;  // attrs 64..84
        } else {
            v0[b] = v1[b] = v2[b] = 0.f;
        }
    }

    #pragma unroll
    for (int b = 0; b < 4; b++) {
        int gi = g0 + b;
        if (gi >= TOT) break;

        // first-max over class scores j in [5,85). scores in [0,1) => uint-monotonic
        unsigned f1 = __float_as_uint(v1[b]);
        unsigned bf = f1; int bj = lane + 32;                   // j=32..63, always valid
        unsigned f0 = __float_as_uint(v0[b]);
        if (lane >= 5 && f0 >= bf) { bf = f0; bj = lane; }      // lower idx wins ties
        unsigned f2 = __float_as_uint(v2[b]);
        if (lane < 21 && f2 > bf)  { bf = f2; bj = lane + 64; } // higher idx on strict > only

        unsigned vmax = __reduce_max_sync(0xffffffffu, bf);
        unsigned jc   = (bf == vmax) ? (unsigned)bj : 255u;
        unsigned jmin = __reduce_min_sync(0xffffffffu, jc);

        float cx = __shfl_sync(0xffffffffu, v0[b], 0);
        float cy = __shfl_sync(0xffffffffu, v0[b], 1);
        float w  = __shfl_sync(0xffffffffu, v0[b], 2);
        float h  = __shfl_sync(0xffffffffu, v0[b], 3);
        float ob = __shfl_sync(0xffffffffu, v0[b], 4);

        // zero-fill this box's output row (kept rows overwritten by nms kernel)
        if (lane < 2)
            ((float4*)(out + (size_t)gi * 8))[lane] = make_float4(0.f, 0.f, 0.f, 0.f);

        if (lane == 0) {
            float ms = __uint_as_float(vmax);
            if (ob > CONF_T && ms > SCORE_T) {
                int cls  = (int)jmin - 5;
                int cidx = ((gi >= NB) ? NC : 0) + cls;
                int pos  = atomicAdd(&g_cnt[cidx], 1);
                int o    = cidx * NB + pos;
                g_lidx[o] = gi;
                g_lkey[o] = ob;
                g_lms [o] = ms;
                g_lbox[o] = make_float4(cx - w * 0.5f, cy - h * 0.5f,
                                        cx + w * 0.5f, cy + h * 0.5f);
            }
        }
    }
}

// 64-bit shfl helper
__device__ __forceinline__ unsigned long long shfl64(unsigned long long v, int src) {
    unsigned lo = (unsigned)v, hi = (unsigned)(v >> 32);
    lo = __shfl_sync(0xffffffffu, lo, src);
    hi = __shfl_sync(0xffffffffu, hi, src);
    return ((unsigned long long)hi << 32) | lo;
}

// ===== kernel 2: per-(image,class) bitmask NMS + direct output (PDL) =====
__global__ __launch_bounds__(128) void nms_out_kernel(float* __restrict__ out) {
    const int c   = blockIdx.x;             // 0 .. NCLS-1
    const int tid = threadIdx.x;
    const int base = c * NB;

#if __CUDA_ARCH__ >= 900
    cudaGridDependencySynchronize();        // PDL: wait for prep's writes
#endif

    // speculative single-epoch loads: k + this thread's list slot, all in flight
    const int   k        = g_cnt[c];
    const float spec_key = g_lkey[base + tid];   // always in-bounds (tid < 128 << NB)
    const int   spec_idx = g_lidx[base + tid];
    const float spec_ms  = g_lms [base + tid];
    const float4 spec_box = g_lbox[base + tid];

    if (tid == 0) g_cnt[c] = 0;             // self-reset for next graph replay
    if (k == 0) return;

    const float batch = (c >= NC) ? 1.0f : 0.0f;
    const float fcls  = (float)(c - ((c >= NC) ? NC : 0));

    __shared__ float    s_key[SMAX];
    __shared__ int      s_idx[SMAX];
    __shared__ float4   s_sbox[SMAX];
    __shared__ float    s_skey[SMAX];
    __shared__ float    s_sms[SMAX];
    __shared__ int      s_sidx[SMAX];
    __shared__ unsigned s_mask[SMAX * WMAX];

    if (k <= 128) {
        // ---------- register-fed fast path (no further global loads) ----------
        s_key[tid] = spec_key;              // lanes >= k hold garbage, never read
        s_idx[tid] = spec_idx;
        __syncthreads();

        // rank = # of (key desc, idx asc)-greater elements  -> deterministic sort
        if (tid < k) {
            float sp = spec_key; int ip = spec_idx;
            int r = 0;
            for (int q = 0; q < k; q++) {
                float sq = s_key[q]; int iq = s_idx[q];
                r += (sq > sp) || (sq == sp && iq < ip);
            }
            s_sbox[r] = spec_box;           // scatter from registers
            s_sms[r]  = spec_ms;
            s_skey[r] = sp;
            s_sidx[r] = ip;
        }
        __syncthreads();

        const int W = (k + 31) >> 5;        // <= 4
        // parallel suppression-bit matrix: thread owns (row r, word w)
        for (int t = tid; t < k * W; t += 128) {
            int r = t / W;
            int w = t - r * W;
            float4 br    = s_sbox[r];
            float  areaR = (br.z - br.x) * (br.w - br.y);
            unsigned m = 0;
            int pbase = w << 5;
            #pragma unroll 4
            for (int j = 0; j < 32; j++) {
                int p = pbase + j;
                if (p > r && p < k) {
                    float4 bp = s_sbox[p];
                    float iw = fminf(br.z, bp.z) - fmaxf(br.x, bp.x); iw = fmaxf(iw, 0.f);
                    float ih = fminf(br.w, bp.w) - fmaxf(br.y, bp.y); ih = fmaxf(ih, 0.f);
                    float inter = iw * ih;
                    float areaP = (bp.z - bp.x) * (bp.w - bp.y);
                    float iou   = inter / (areaR + areaP - inter + 1e-16f);
                    if (iou >= NMS_T) m |= (1u << j);
                }
            }
            s_mask[t] = m;
        }
        __syncthreads();

        if (tid < 32) {
            if (k <= 64) {
                // ---- register-resident scan: lane l holds rows l and l+32 ----
                unsigned long long rowlo = 0ull, rowhi = 0ull;
                if (tid < k)
                    rowlo = (unsigned long long)s_mask[tid * W] |
                            ((W > 1) ? ((unsigned long long)s_mask[tid * W + 1] << 32) : 0ull);
                if (tid + 32 < k)
                    rowhi = (unsigned long long)s_mask[(tid + 32) * W] |
                            ((W > 1) ? ((unsigned long long)s_mask[(tid + 32) * W + 1] << 32) : 0ull);

                unsigned long long removed = 0ull;     // replicated in all lanes
                for (int r = 0; r < k; r++) {
                    unsigned long long sel = (r < 32) ? rowlo : rowhi;
                    unsigned long long row = shfl64(sel, r & 31);
                    if (!((removed >> r) & 1ull)) removed |= row;
                }
                // write kept rows
                #pragma unroll
                for (int i = 0; i < 2; i++) {
                    int p = (i << 5) + tid;
                    if (p < k && !((removed >> p) & 1ull)) {
                        int    gi = s_sidx[p];
                        float4 bx = s_sbox[p];
                        float4* po = (float4*)(out + (size_t)gi * 8);
                        po[0] = make_float4(batch, bx.x, bx.y, bx.z);
                        po[1] = make_float4(bx.w, s_skey[p], s_sms[p], fcls);
                    }
                }
            } else {
                // ---- smem scan (64 < k <= 128): lane w owns removed-word w ----
                unsigned removed = 0;
                for (int r = 0; r < k; r++) {
                    unsigned word = __shfl_sync(0xffffffffu, removed, r >> 5);
                    if (!((word >> (r & 31)) & 1u))
                        if (tid < W) removed |= s_mask[r * W + tid];
                }
                for (int i = 0; (i << 5) < k; i++) {
                    int p = (i << 5) + tid;
                    unsigned wrd = __shfl_sync(0xffffffffu, removed, i);
                    if (p < k && !((wrd >> tid) & 1u)) {
                        int    gi = s_sidx[p];
                        float4 bx = s_sbox[p];
                        float4* po = (float4*)(out + (size_t)gi * 8);
                        po[0] = make_float4(batch, bx.x, bx.y, bx.z);
                        po[1] = make_float4(bx.w, s_skey[p], s_sms[p], fcls);
                    }
                }
            }
        }
    } else if (k <= SMAX) {
        // ---------- mid path (128 < k <= 256) ----------
        const int W = (k + 31) >> 5;
        for (int p = tid; p < k; p += 128) {
            s_key[p] = g_lkey[base + p];
            s_idx[p] = g_lidx[base + p];
        }
        __syncthreads();
        for (int p = tid; p < k; p += 128) {
            float sp = s_key[p]; int ip = s_idx[p];
            int r = 0;
            for (int q = 0; q < k; q++) {
                float sq = s_key[q]; int iq = s_idx[q];
                r += (sq > sp) || (sq == sp && iq < ip);
            }
            s_sbox[r] = g_lbox[base + p];
            s_sms[r]  = g_lms[base + p];
            s_skey[r] = sp;
            s_sidx[r] = ip;
        }
        __syncthreads();
        for (int t = tid; t < k * W; t += 128) {
            int r = t / W;
            int w = t - r * W;
            float4 br    = s_sbox[r];
            float  areaR = (br.z - br.x) * (br.w - br.y);
            unsigned m = 0;
            int pbase = w << 5;
            for (int j = 0; j < 32; j++) {
                int p = pbase + j;
                if (p > r && p < k) {
                    float4 bp = s_sbox[p];
                    float iw = fminf(br.z, bp.z) - fmaxf(br.x, bp.x); iw = fmaxf(iw, 0.f);
                    float ih = fminf(br.w, bp.w) - fmaxf(br.y, bp.y); ih = fmaxf(ih, 0.f);
                    float inter = iw * ih;
                    float areaP = (bp.z - bp.x) * (bp.w - bp.y);
                    float iou   = inter / (areaR + areaP - inter + 1e-16f);
                    if (iou >= NMS_T) m |= (1u << j);
                }
            }
            s_mask[t] = m;
        }
        __syncthreads();
        if (tid < 32) {
            unsigned removed = 0;
            for (int r = 0; r < k; r++) {
                unsigned word = __shfl_sync(0xffffffffu, removed, r >> 5);
                if (!((word >> (r & 31)) & 1u))
                    if (tid < W) removed |= s_mask[r * W + tid];
            }
            for (int i = 0; (i << 5) < k; i++) {
                int p = (i << 5) + tid;
                unsigned wrd = __shfl_sync(0xffffffffu, removed, i);
                if (p < k && !((wrd >> tid) & 1u)) {
                    int    gi = s_sidx[p];
                    float4 bx = s_sbox[p];
                    float4* po = (float4*)(out + (size_t)gi * 8);
                    po[0] = make_float4(batch, bx.x, bx.y, bx.z);
                    po[1] = make_float4(bx.w, s_skey[p], s_sms[p], fcls);
                }
            }
        }
    } else {
        // ---------- global fallback (k > 256; essentially never taken) ----------
        __shared__ unsigned char keptg[NB];
        for (int p = tid; p < k; p += 128) {
            float sp = g_lkey[base + p];
            int   ip = g_lidx[base + p];
            int r = 0;
            for (int q = 0; q < k; q++) {
                float sq = g_lkey[base + q];
                int   iq = g_lidx[base + q];
                r += (sq > sp) || (sq == sp && iq < ip);
            }
            g_srt[base + r] = p;
        }
        __syncthreads();
        for (int p = tid; p < k; p += 128) keptg[p] = 1;
        __syncthreads();
        if (tid < 32) {
            for (int r = 0; r < k; r++) {
                if (!keptg[r]) continue;
                float4 br    = g_lbox[base + g_srt[base + r]];
                float  areaR = (br.z - br.x) * (br.w - br.y);
                for (int p = r + 1 + tid; p < k; p += 32) {
                    if (!keptg[p]) continue;
                    float4 bp = g_lbox[base + g_srt[base + p]];
                    float iw = fminf(br.z, bp.z) - fmaxf(br.x, bp.x); iw = fmaxf(iw, 0.f);
                    float ih = fminf(br.w, bp.w) - fmaxf(br.y, bp.y); ih = fmaxf(ih, 0.f);
                    float inter = iw * ih;
                    float areaP = (bp.z - bp.x) * (bp.w - bp.y);
                    float iou   = inter / (areaR + areaP - inter + 1e-16f);
                    if (iou >= NMS_T) keptg[p] = 0;
                }
                __syncwarp();
            }
            for (int r = tid; r < k; r += 32) {
                if (keptg[r]) {
                    int    lp = g_srt[base + r];
                    int    gi = g_lidx[base + lp];
                    float4 bx = g_lbox[base + lp];
                    float4* po = (float4*)(out + (size_t)gi * 8);
                    po[0] = make_float4(batch, bx.x, bx.y, bx.z);
                    po[1] = make_float4(bx.w, g_lkey[base + lp], g_lms[base + lp], fcls);
                }
            }
        }
    }
}

extern "C" void kernel_launch(void* const* d_in, const int* in_sizes, int n_in,
                              void* d_out, int out_size) {
    const float* x   = (const float*)d_in[0];
    float*       out = (float*)d_out;

    // 4 boxes per warp, 8 warps per block
    int prep_blocks = (TOT + 31) / 32;
    prep_kernel<<<prep_blocks, 256>>>(x, out);

    // nms with programmatic dependent launch: dispatch overlaps prep's tail,
    // device-side cudaGridDependencySynchronize() provides the data dependency.
    cudaLaunchConfig_t cfg = {};
    cfg.gridDim  = dim3(NCLS, 1, 1);
    cfg.blockDim = dim3(128, 1, 1);
    cfg.dynamicSmemBytes = 0;
    cfg.stream = 0;
    cudaLaunchAttribute attr[1];
    attr[0].id = cudaLaunchAttributeProgrammaticStreamSerialization;
    attr[0].val.programmaticStreamSerializationAllowed = 1;
    cfg.attrs = attr;
    cfg.numAttrs = 1;
    cudaError_t e = cudaLaunchKernelEx(&cfg, nms_out_kernel, out);
    if (e != cudaSuccess) {
        // fallback: plain launch (keeps graph valid if PDL capture unsupported)
        nms_out_kernel<<<NCLS, 128>>>(out);
    }
}

// round 14
// speedup vs baseline: 1.1199x; 1.1199x over previous
#include <cuda_runtime.h>

#define BS 2
#define NB 6300
#define NA 85
#define NC 80
#define TOT  (BS * NB)
#define NCLS (BS * NC)

#define CONF_T  0.5f
#define NMS_T   0.4f
#define SCORE_T 0.3f

#define SMAX 256             // mid-path capacity
#define WMAX 8               // mask words per row at SMAX

// -------- device scratch (static allocation; zero-initialized) --------
__device__ int    g_cnt[NCLS];           // self-reset in nms each run
__device__ int    g_lidx[NCLS * NB];     // per-class lists: global box idx
__device__ float  g_lkey[NCLS * NB];     //   objectness (sort key)
__device__ float  g_lms [NCLS * NB];     //   max class score
__device__ float4 g_lbox[NCLS * NB];     //   corners
__device__ int    g_srt [NCLS * NB];     // fallback path only

// ================= kernel 1: prep — 4 boxes per warp =================
__global__ __launch_bounds__(256) void prep_kernel(const float* __restrict__ x,
                                                   float* __restrict__ out) {
    const int warp = (blockIdx.x * blockDim.x + threadIdx.x) >> 5;
    const int lane = threadIdx.x & 31;
    const int g0   = warp * 4;

    // issue all loads for 4 boxes up front (12 independent LDGs in flight)
    float v0[4], v1[4], v2[4];
    #pragma unroll
    for (int b = 0; b < 4; b++) {
        int gi = g0 + b;
        if (gi < TOT) {
            const float* p = x + (size_t)gi * NA;
            v0[b] = p[lane];                           // attrs 0..31
            v1[b] = p[lane + 32];                      // attrs 32..63
            v2[b] = (lane < 21) ? p[lane + 64] : 0.f;  // attrs 64..84
        } else {
            v0[b] = v1[b] = v2[b] = 0.f;
        }
    }

    #pragma unroll
    for (int b = 0; b < 4; b++) {
        int gi = g0 + b;
        if (gi >= TOT) break;

        // first-max over class scores j in [5,85). scores in [0,1) => uint-monotonic
        unsigned f1 = __float_as_uint(v1[b]);
        unsigned bf = f1; int bj = lane + 32;                   // j=32..63, always valid
        unsigned f0 = __float_as_uint(v0[b]);
        if (lane >= 5 && f0 >= bf) { bf = f0; bj = lane; }      // lower idx wins ties
        unsigned f2 = __float_as_uint(v2[b]);
        if (lane < 21 && f2 > bf)  { bf = f2; bj = lane + 64; } // higher idx on strict > only

        unsigned vmax = __reduce_max_sync(0xffffffffu, bf);
        unsigned jc   = (bf == vmax) ? (unsigned)bj : 255u;
        unsigned jmin = __reduce_min_sync(0xffffffffu, jc);

        float cx = __shfl_sync(0xffffffffu, v0[b], 0);
        float cy = __shfl_sync(0xffffffffu, v0[b], 1);
        float w  = __shfl_sync(0xffffffffu, v0[b], 2);
        float h  = __shfl_sync(0xffffffffu, v0[b], 3);
        float ob = __shfl_sync(0xffffffffu, v0[b], 4);

        // zero-fill this box's output row (kept rows overwritten by nms kernel)
        if (lane < 2)
            ((float4*)(out + (size_t)gi * 8))[lane] = make_float4(0.f, 0.f, 0.f, 0.f);

        if (lane == 0) {
            float ms = __uint_as_float(vmax);
            if (ob > CONF_T && ms > SCORE_T) {
                int cls  = (int)jmin - 5;
                int cidx = ((gi >= NB) ? NC : 0) + cls;
                int pos  = atomicAdd(&g_cnt[cidx], 1);
                int o    = cidx * NB + pos;
                g_lidx[o] = gi;
                g_lkey[o] = ob;
                g_lms [o] = ms;
                g_lbox[o] = make_float4(cx - w * 0.5f, cy - h * 0.5f,
                                        cx + w * 0.5f, cy + h * 0.5f);
            }
        }
    }
}

// 64-bit shfl helper
__device__ __forceinline__ unsigned long long shfl64(unsigned long long v, int src) {
    unsigned lo = (unsigned)v, hi = (unsigned)(v >> 32);
    lo = __shfl_sync(0xffffffffu, lo, src);
    hi = __shfl_sync(0xffffffffu, hi, src);
    return ((unsigned long long)hi << 32) | lo;
}

// ===== kernel 2: per-(image,class) bitmask NMS + direct output (PDL) =====
__global__ __launch_bounds__(128) void nms_out_kernel(float* __restrict__ out) {
    const int c   = blockIdx.x;             // 0 .. NCLS-1
    const int tid = threadIdx.x;
    const int base = c * NB;

#if __CUDA_ARCH__ >= 900
    cudaGridDependencySynchronize();        // PDL: wait for prep's writes
#endif

    // speculative single-epoch loads: k + this thread's list slot, all in flight
    const int   k        = g_cnt[c];
    const float spec_key = g_lkey[base + tid];   // always in-bounds (tid < 128 << NB)
    const int   spec_idx = g_lidx[base + tid];
    const float spec_ms  = g_lms [base + tid];
    const float4 spec_box = g_lbox[base + tid];

    if (tid == 0) g_cnt[c] = 0;             // self-reset for next graph replay
    if (k == 0) return;

    const float batch = (c >= NC) ? 1.0f : 0.0f;
    const float fcls  = (float)(c - ((c >= NC) ? NC : 0));

    __shared__ float    s_key[SMAX];
    __shared__ int      s_idx[SMAX];
    __shared__ float4   s_sbox[SMAX];
    __shared__ float    s_skey[SMAX];
    __shared__ float    s_sms[SMAX];
    __shared__ int      s_sidx[SMAX];
    __shared__ unsigned s_mask[SMAX * WMAX];

    if (k <= 128) {
        // ---------- register-fed fast path (no further global loads) ----------
        s_key[tid] = spec_key;              // lanes >= k hold garbage, never read
        s_idx[tid] = spec_idx;
        __syncthreads();

        // rank = # of (key desc, idx asc)-greater elements  -> deterministic sort
        if (tid < k) {
            float sp = spec_key; int ip = spec_idx;
            int r = 0;
            for (int q = 0; q < k; q++) {
                float sq = s_key[q]; int iq = s_idx[q];
                r += (sq > sp) || (sq == sp && iq < ip);
            }
            s_sbox[r] = spec_box;           // scatter from registers
            s_sms[r]  = spec_ms;
            s_skey[r] = sp;
            s_sidx[r] = ip;
        }
        __syncthreads();

        const int W = (k + 31) >> 5;        // <= 4
        // parallel suppression-bit matrix: thread owns (row r, word w)
        for (int t = tid; t < k * W; t += 128) {
            int r = t / W;
            int w = t - r * W;
            float4 br    = s_sbox[r];
            float  areaR = (br.z - br.x) * (br.w - br.y);
            unsigned m = 0;
            int pbase = w << 5;
            #pragma unroll 4
            for (int j = 0; j < 32; j++) {
                int p = pbase + j;
                if (p > r && p < k) {
                    float4 bp = s_sbox[p];
                    float iw = fminf(br.z, bp.z) - fmaxf(br.x, bp.x); iw = fmaxf(iw, 0.f);
                    float ih = fminf(br.w, bp.w) - fmaxf(br.y, bp.y); ih = fmaxf(ih, 0.f);
                    float inter = iw * ih;
                    float areaP = (bp.z - bp.x) * (bp.w - bp.y);
                    float iou   = inter / (areaR + areaP - inter + 1e-16f);
                    if (iou >= NMS_T) m |= (1u << j);
                }
            }
            s_mask[t] = m;
        }
        __syncthreads();

        if (tid < 32) {
            if (k <= 64) {
                // ---- register-resident scan: lane l holds rows l and l+32 ----
                unsigned long long rowlo = 0ull, rowhi = 0ull;
                if (tid < k)
                    rowlo = (unsigned long long)s_mask[tid * W] |
                            ((W > 1) ? ((unsigned long long)s_mask[tid * W + 1] << 32) : 0ull);
                if (tid + 32 < k)
                    rowhi = (unsigned long long)s_mask[(tid + 32) * W] |
                            ((W > 1) ? ((unsigned long long)s_mask[(tid + 32) * W + 1] << 32) : 0ull);

                unsigned long long removed = 0ull;     // replicated in all lanes
                for (int r = 0; r < k; r++) {
                    unsigned long long sel = (r < 32) ? rowlo : rowhi;
                    unsigned long long row = shfl64(sel, r & 31);
                    if (!((removed >> r) & 1ull)) removed |= row;
                }
                // write kept rows
                #pragma unroll
                for (int i = 0; i < 2; i++) {
                    int p = (i << 5) + tid;
                    if (p < k && !((removed >> p) & 1ull)) {
                        int    gi = s_sidx[p];
                        float4 bx = s_sbox[p];
                        float4* po = (float4*)(out + (size_t)gi * 8);
                        po[0] = make_float4(batch, bx.x, bx.y, bx.z);
                        po[1] = make_float4(bx.w, s_skey[p], s_sms[p], fcls);
                    }
                }
            } else {
                // ---- smem scan (64 < k <= 128): lane w owns removed-word w ----
                unsigned removed = 0;
                for (int r = 0; r < k; r++) {
                    unsigned word = __shfl_sync(0xffffffffu, removed, r >> 5);
                    if (!((word >> (r & 31)) & 1u))
                        if (tid < W) removed |= s_mask[r * W + tid];
                }
                for (int i = 0; (i << 5) < k; i++) {
                    int p = (i << 5) + tid;
                    unsigned wrd = __shfl_sync(0xffffffffu, removed, i);
                    if (p < k && !((wrd >> tid) & 1u)) {
                        int    gi = s_sidx[p];
                        float4 bx = s_sbox[p];
                        float4* po = (float4*)(out + (size_t)gi * 8);
                        po[0] = make_float4(batch, bx.x, bx.y, bx.z);
                        po[1] = make_float4(bx.w, s_skey[p], s_sms[p], fcls);
                    }
                }
            }
        }
    } else if (k <= SMAX) {
        // ---------- mid path (128 < k <= 256) ----------
        const int W = (k + 31) >> 5;
        for (int p = tid; p < k; p += 128) {
            s_key[p] = g_lkey[base + p];
            s_idx[p] = g_lidx[base + p];
        }
        __syncthreads();
        for (int p = tid; p < k; p += 128) {
            float sp = s_key[p]; int ip = s_idx[p];
            int r = 0;
            for (int q = 0; q < k; q++) {
                float sq = s_key[q]; int iq = s_idx[q];
                r += (sq > sp) || (sq == sp && iq < ip);
            }
            s_sbox[r] = g_lbox[base + p];
            s_sms[r]  = g_lms[base + p];
            s_skey[r] = sp;
            s_sidx[r] = ip;
        }
        __syncthreads();
        for (int t = tid; t < k * W; t += 128) {
            int r = t / W;
            int w = t - r * W;
            float4 br    = s_sbox[r];
            float  areaR = (br.z - br.x) * (br.w - br.y);
            unsigned m = 0;
            int pbase = w << 5;
            for (int j = 0; j < 32; j++) {
                int p = pbase + j;
                if (p > r && p < k) {
                    float4 bp = s_sbox[p];
                    float iw = fminf(br.z, bp.z) - fmaxf(br.x, bp.x); iw = fmaxf(iw, 0.f);
                    float ih = fminf(br.w, bp.w) - fmaxf(br.y, bp.y); ih = fmaxf(ih, 0.f);
                    float inter = iw * ih;
                    float areaP = (bp.z - bp.x) * (bp.w - bp.y);
                    float iou   = inter / (areaR + areaP - inter + 1e-16f);
                    if (iou >= NMS_T) m |= (1u << j);
                }
            }
            s_mask[t] = m;
        }
        __syncthreads();
        if (tid < 32) {
            unsigned removed = 0;
            for (int r = 0; r < k; r++) {
                unsigned word = __shfl_sync(0xffffffffu, removed, r >> 5);
                if (!((word >> (r & 31)) & 1u))
                    if (tid < W) removed |= s_mask[r * W + tid];
            }
            for (int i = 0; (i << 5) < k; i++) {
                int p = (i << 5) + tid;
                unsigned wrd = __shfl_sync(0xffffffffu, removed, i);
                if (p < k && !((wrd >> tid) & 1u)) {
                    int    gi = s_sidx[p];
                    float4 bx = s_sbox[p];
                    float4* po = (float4*)(out + (size_t)gi * 8);
                    po[0] = make_float4(batch, bx.x, bx.y, bx.z);
                    po[1] = make_float4(bx.w, s_skey[p], s_sms[p], fcls);
                }
            }
        }
    } else {
        // ---------- global fallback (k > 256; essentially never taken) ----------
        __shared__ unsigned char keptg[NB];
        for (int p = tid; p < k; p += 128) {
            float sp = g_lkey[base + p];
            int   ip = g_lidx[base + p];
            int r = 0;
            for (int q = 0; q < k; q++) {
                float sq = g_lkey[base + q];
                int   iq = g_lidx[base + q];
                r += (sq > sp) || (sq == sp && iq < ip);
            }
            g_srt[base + r] = p;
        }
        __syncthreads();
        for (int p = tid; p < k; p += 128) keptg[p] = 1;
        __syncthreads();
        if (tid < 32) {
            for (int r = 0; r < k; r++) {
                if (!keptg[r]) continue;
                float4 br    = g_lbox[base + g_srt[base + r]];
                float  areaR = (br.z - br.x) * (br.w - br.y);
                for (int p = r + 1 + tid; p < k; p += 32) {
                    if (!keptg[p]) continue;
                    float4 bp = g_lbox[base + g_srt[base + p]];
                    float iw = fminf(br.z, bp.z) - fmaxf(br.x, bp.x); iw = fmaxf(iw, 0.f);
                    float ih = fminf(br.w, bp.w) - fmaxf(br.y, bp.y); ih = fmaxf(ih, 0.f);
                    float inter = iw * ih;
                    float areaP = (bp.z - bp.x) * (bp.w - bp.y);
                    float iou   = inter / (areaR + areaP - inter + 1e-16f);
                    if (iou >= NMS_T) keptg[p] = 0;
                }
                __syncwarp();
            }
            for (int r = tid; r < k; r += 32) {
                if (keptg[r]) {
                    int    lp = g_srt[base + r];
                    int    gi = g_lidx[base + lp];
                    float4 bx = g_lbox[base + lp];
                    float4* po = (float4*)(out + (size_t)gi * 8);
                    po[0] = make_float4(batch, bx.x, bx.y, bx.z);
                    po[1] = make_float4(bx.w, g_lkey[base + lp], g_lms[base + lp], fcls);
                }
            }
        }
    }
}

extern "C" void kernel_launch(void* const* d_in, const int* in_sizes, int n_in,
                              void* d_out, int out_size) {
    const float* x   = (const float*)d_in[0];
    float*       out = (float*)d_out;

    // 4 boxes per warp, 8 warps per block
    int prep_blocks = (TOT + 31) / 32;
    prep_kernel<<<prep_blocks, 256>>>(x, out);

    // nms with programmatic dependent launch: dispatch overlaps prep's tail,
    // device-side cudaGridDependencySynchronize() provides the data dependency.
    cudaLaunchConfig_t cfg = {};
    cfg.gridDim  = dim3(NCLS, 1, 1);
    cfg.blockDim = dim3(128, 1, 1);
    cfg.dynamicSmemBytes = 0;
    cfg.stream = 0;
    cudaLaunchAttribute attr[1];
    attr[0].id = cudaLaunchAttributeProgrammaticStreamSerialization;
    attr[0].val.programmaticStreamSerializationAllowed = 1;
    cfg.attrs = attr;
    cfg.numAttrs = 1;
    cudaError_t e = cudaLaunchKernelEx(&cfg, nms_out_kernel, out);
    if (e != cudaSuccess) {
        // fallback: plain launch (keeps graph valid if PDL capture unsupported)
        nms_out_kernel<<<NCLS, 128>>>(out);
    }
}

// round 15
// speedup vs baseline: 1.1218x; 1.0017x over previous
#include <cuda_runtime.h>

#define BS 2
#define NB 6300
#define NA 85
#define NC 80
#define TOT  (BS * NB)
#define NCLS (BS * NC)

#define CONF_T  0.5f
#define NMS_T   0.4f
#define SCORE_T 0.3f

#define SMAX 256             // mid-path capacity
#define WMAX 8               // mask words per row at SMAX

// -------- device scratch (static allocation; zero-initialized) --------
__device__ int    g_cnt[NCLS];           // self-reset in nms each run
__device__ int    g_lidx[NCLS * NB];     // per-class lists: global box idx
__device__ float  g_lkey[NCLS * NB];     //   objectness (sort key)
__device__ float  g_lms [NCLS * NB];     //   max class score
__device__ float4 g_lbox[NCLS * NB];     //   corners
__device__ int    g_srt [NCLS * NB];     // fallback path only

// ================= kernel 1: prep — 4 boxes per warp =================
__global__ __launch_bounds__(256) void prep_kernel(const float* __restrict__ x,
                                                   float* __restrict__ out) {
    const int warp = (blockIdx.x * blockDim.x + threadIdx.x) >> 5;
    const int lane = threadIdx.x & 31;
    const int g0   = warp * 4;

    // issue all loads for 4 boxes up front (12 independent LDGs in flight)
    float v0[4], v1[4], v2[4];
    #pragma unroll
    for (int b = 0; b < 4; b++) {
        int gi = g0 + b;
        if (gi < TOT) {
            const float* p = x + (size_t)gi * NA;
            v0[b] = p[lane];                           // attrs 0..31
            v1[b] = p[lane + 32];                      // attrs 32..63
            v2[b] = (lane < 21) ? p[lane + 64] : 0.f;  // attrs 64..84
        } else {
            v0[b] = v1[b] = v2[b] = 0.f;
        }
    }

    #pragma unroll
    for (int b = 0; b < 4; b++) {
        int gi = g0 + b;
        if (gi >= TOT) break;

        // first-max over class scores j in [5,85). scores in [0,1) => uint-monotonic
        unsigned f1 = __float_as_uint(v1[b]);
        unsigned bf = f1; int bj = lane + 32;                   // j=32..63, always valid
        unsigned f0 = __float_as_uint(v0[b]);
        if (lane >= 5 && f0 >= bf) { bf = f0; bj = lane; }      // lower idx wins ties
        unsigned f2 = __float_as_uint(v2[b]);
        if (lane < 21 && f2 > bf)  { bf = f2; bj = lane + 64; } // higher idx on strict > only

        unsigned vmax = __reduce_max_sync(0xffffffffu, bf);
        unsigned jc   = (bf == vmax) ? (unsigned)bj : 255u;
        unsigned jmin = __reduce_min_sync(0xffffffffu, jc);

        float cx = __shfl_sync(0xffffffffu, v0[b], 0);
        float cy = __shfl_sync(0xffffffffu, v0[b], 1);
        float w  = __shfl_sync(0xffffffffu, v0[b], 2);
        float h  = __shfl_sync(0xffffffffu, v0[b], 3);
        float ob = __shfl_sync(0xffffffffu, v0[b], 4);

        // zero-fill this box's output row (kept rows overwritten by nms kernel)
        if (lane < 2)
            ((float4*)(out + (size_t)gi * 8))[lane] = make_float4(0.f, 0.f, 0.f, 0.f);

        if (lane == 0) {
            float ms = __uint_as_float(vmax);
            if (ob > CONF_T && ms > SCORE_T) {
                int cls  = (int)jmin - 5;
                int cidx = ((gi >= NB) ? NC : 0) + cls;
                int pos  = atomicAdd(&g_cnt[cidx], 1);
                int o    = cidx * NB + pos;
                g_lidx[o] = gi;
                g_lkey[o] = ob;
                g_lms [o] = ms;
                g_lbox[o] = make_float4(cx - w * 0.5f, cy - h * 0.5f,
                                        cx + w * 0.5f, cy + h * 0.5f);
            }
        }
    }
}

// 64-bit shfl helper
__device__ __forceinline__ unsigned long long shfl64(unsigned long long v, int src) {
    unsigned lo = (unsigned)v, hi = (unsigned)(v >> 32);
    lo = __shfl_sync(0xffffffffu, lo, src);
    hi = __shfl_sync(0xffffffffu, hi, src);
    return ((unsigned long long)hi << 32) | lo;
}

// ===== kernel 2: per-(image,class) bitmask NMS + direct output (PDL) =====
__global__ __launch_bounds__(128) void nms_out_kernel(float* __restrict__ out) {
    const int c   = blockIdx.x;             // 0 .. NCLS-1
    const int tid = threadIdx.x;
    const int base = c * NB;

#if __CUDA_ARCH__ >= 900
    cudaGridDependencySynchronize();        // PDL: wait for prep's writes
#endif

    // speculative single-epoch loads: k + this thread's list slot, all in flight
    const int   k        = g_cnt[c];
    const float spec_key = g_lkey[base + tid];   // always in-bounds (tid < 128 << NB)
    const int   spec_idx = g_lidx[base + tid];
    const float spec_ms  = g_lms [base + tid];
    const float4 spec_box = g_lbox[base + tid];

    if (tid == 0) g_cnt[c] = 0;             // self-reset for next graph replay
    if (k == 0) return;

    const float batch = (c >= NC) ? 1.0f : 0.0f;
    const float fcls  = (float)(c - ((c >= NC) ? NC : 0));

    __shared__ float    s_key[SMAX];
    __shared__ int      s_idx[SMAX];
    __shared__ float4   s_sbox[SMAX];
    __shared__ float    s_skey[SMAX];
    __shared__ float    s_sms[SMAX];
    __shared__ int      s_sidx[SMAX];
    __shared__ unsigned s_mask[SMAX * WMAX];

    if (k <= 128) {
        // ---------- register-fed fast path (no further global loads) ----------
        s_key[tid] = spec_key;              // lanes >= k hold garbage, never read
        s_idx[tid] = spec_idx;
        __syncthreads();

        // rank = # of (key desc, idx asc)-greater elements  -> deterministic sort
        if (tid < k) {
            float sp = spec_key; int ip = spec_idx;
            int r = 0;
            for (int q = 0; q < k; q++) {
                float sq = s_key[q]; int iq = s_idx[q];
                r += (sq > sp) || (sq == sp && iq < ip);
            }
            s_sbox[r] = spec_box;           // scatter from registers
            s_sms[r]  = spec_ms;
            s_skey[r] = sp;
            s_sidx[r] = ip;
        }
        __syncthreads();

        const int W = (k + 31) >> 5;        // <= 4
        // parallel suppression-bit matrix: thread owns (row r, word w)
        for (int t = tid; t < k * W; t += 128) {
            int r = t / W;
            int w = t - r * W;
            float4 br    = s_sbox[r];
            float  areaR = (br.z - br.x) * (br.w - br.y);
            unsigned m = 0;
            int pbase = w << 5;
            #pragma unroll 4
            for (int j = 0; j < 32; j++) {
                int p = pbase + j;
                if (p > r && p < k) {
                    float4 bp = s_sbox[p];
                    float iw = fminf(br.z, bp.z) - fmaxf(br.x, bp.x); iw = fmaxf(iw, 0.f);
                    float ih = fminf(br.w, bp.w) - fmaxf(br.y, bp.y); ih = fmaxf(ih, 0.f);
                    float inter = iw * ih;
                    float areaP = (bp.z - bp.x) * (bp.w - bp.y);
                    float iou   = inter / (areaR + areaP - inter + 1e-16f);
                    if (iou >= NMS_T) m |= (1u << j);
                }
            }
            s_mask[t] = m;
        }
        __syncthreads();

        if (tid < 32) {
            if (k <= 64) {
                // ---- register-resident scan: lane l holds rows l and l+32 ----
                unsigned long long rowlo = 0ull, rowhi = 0ull;
                if (tid < k)
                    rowlo = (unsigned long long)s_mask[tid * W] |
                            ((W > 1) ? ((unsigned long long)s_mask[tid * W + 1] << 32) : 0ull);
                if (tid + 32 < k)
                    rowhi = (unsigned long long)s_mask[(tid + 32) * W] |
                            ((W > 1) ? ((unsigned long long)s_mask[(tid + 32) * W + 1] << 32) : 0ull);

                unsigned long long removed = 0ull;     // replicated in all lanes
                for (int r = 0; r < k; r++) {
                    unsigned long long sel = (r < 32) ? rowlo : rowhi;
                    unsigned long long row = shfl64(sel, r & 31);
                    if (!((removed >> r) & 1ull)) removed |= row;
                }
                // write kept rows
                #pragma unroll
                for (int i = 0; i < 2; i++) {
                    int p = (i << 5) + tid;
                    if (p < k && !((removed >> p) & 1ull)) {
                        int    gi = s_sidx[p];
                        float4 bx = s_sbox[p];
                        float4* po = (float4*)(out + (size_t)gi * 8);
                        po[0] = make_float4(batch, bx.x, bx.y, bx.z);
                        po[1] = make_float4(bx.w, s_skey[p], s_sms[p], fcls);
                    }
                }
            } else {
                // ---- smem scan (64 < k <= 128): lane w owns removed-word w ----
                unsigned removed = 0;
                for (int r = 0; r < k; r++) {
                    unsigned word = __shfl_sync(0xffffffffu, removed, r >> 5);
                    if (!((word >> (r & 31)) & 1u))
                        if (tid < W) removed |= s_mask[r * W + tid];
                }
                for (int i = 0; (i << 5) < k; i++) {
                    int p = (i << 5) + tid;
                    unsigned wrd = __shfl_sync(0xffffffffu, removed, i);
                    if (p < k && !((wrd >> tid) & 1u)) {
                        int    gi = s_sidx[p];
                        float4 bx = s_sbox[p];
                        float4* po = (float4*)(out + (size_t)gi * 8);
                        po[0] = make_float4(batch, bx.x, bx.y, bx.z);
                        po[1] = make_float4(bx.w, s_skey[p], s_sms[p], fcls);
                    }
                }
            }
        }
    } else if (k <= SMAX) {
        // ---------- mid path (128 < k <= 256) ----------
        const int W = (k + 31) >> 5;
        for (int p = tid; p < k; p += 128) {
            s_key[p] = g_lkey[base + p];
            s_idx[p] = g_lidx[base + p];
        }
        __syncthreads();
        for (int p = tid; p < k; p += 128) {
            float sp = s_key[p]; int ip = s_idx[p];
            int r = 0;
            for (int q = 0; q < k; q++) {
                float sq = s_key[q]; int iq = s_idx[q];
                r += (sq > sp) || (sq == sp && iq < ip);
            }
            s_sbox[r] = g_lbox[base + p];
            s_sms[r]  = g_lms[base + p];
            s_skey[r] = sp;
            s_sidx[r] = ip;
        }
        __syncthreads();
        for (int t = tid; t < k * W; t += 128) {
            int r = t / W;
            int w = t - r * W;
            float4 br    = s_sbox[r];
            float  areaR = (br.z - br.x) * (br.w - br.y);
            unsigned m = 0;
            int pbase = w << 5;
            for (int j = 0; j < 32; j++) {
                int p = pbase + j;
                if (p > r && p < k) {
                    float4 bp = s_sbox[p];
                    float iw = fminf(br.z, bp.z) - fmaxf(br.x, bp.x); iw = fmaxf(iw, 0.f);
                    float ih = fminf(br.w, bp.w) - fmaxf(br.y, bp.y); ih = fmaxf(ih, 0.f);
                    float inter = iw * ih;
                    float areaP = (bp.z - bp.x) * (bp.w - bp.y);
                    float iou   = inter / (areaR + areaP - inter + 1e-16f);
                    if (iou >= NMS_T) m |= (1u << j);
                }
            }
            s_mask[t] = m;
        }
        __syncthreads();
        if (tid < 32) {
            unsigned removed = 0;
            for (int r = 0; r < k; r++) {
                unsigned word = __shfl_sync(0xffffffffu, removed, r >> 5);
                if (!((word >> (r & 31)) & 1u))
                    if (tid < W) removed |= s_mask[r * W + tid];
            }
            for (int i = 0; (i << 5) < k; i++) {
                int p = (i << 5) + tid;
                unsigned wrd = __shfl_sync(0xffffffffu, removed, i);
                if (p < k && !((wrd >> tid) & 1u)) {
                    int    gi = s_sidx[p];
                    float4 bx = s_sbox[p];
                    float4* po = (float4*)(out + (size_t)gi * 8);
                    po[0] = make_float4(batch, bx.x, bx.y, bx.z);
                    po[1] = make_float4(bx.w, s_skey[p], s_sms[p], fcls);
                }
            }
        }
    } else {
        // ---------- global fallback (k > 256; essentially never taken) ----------
        __shared__ unsigned char keptg[NB];
        for (int p = tid; p < k; p += 128) {
            float sp = g_lkey[base + p];
            int   ip = g_lidx[base + p];
            int r = 0;
            for (int q = 0; q < k; q++) {
                float sq = g_lkey[base + q];
                int   iq = g_lidx[base + q];
                r += (sq > sp) || (sq == sp && iq < ip);
            }
            g_srt[base + r] = p;
        }
        __syncthreads();
        for (int p = tid; p < k; p += 128) keptg[p] = 1;
        __syncthreads();
        if (tid < 32) {
            for (int r = 0; r < k; r++) {
                if (!keptg[r]) continue;
                float4 br    = g_lbox[base + g_srt[base + r]];
                float  areaR = (br.z - br.x) * (br.w - br.y);
                for (int p = r + 1 + tid; p < k; p += 32) {
                    if (!keptg[p]) continue;
                    float4 bp = g_lbox[base + g_srt[base + p]];
                    float iw = fminf(br.z, bp.z) - fmaxf(br.x, bp.x); iw = fmaxf(iw, 0.f);
                    float ih = fminf(br.w, bp.w) - fmaxf(br.y, bp.y); ih = fmaxf(ih, 0.f);
                    float inter = iw * ih;
                    float areaP = (bp.z - bp.x) * (bp.w - bp.y);
                    float iou   = inter / (areaR + areaP - inter + 1e-16f);
                    if (iou >= NMS_T) keptg[p] = 0;
                }
                __syncwarp();
            }
            for (int r = tid; r < k; r += 32) {
                if (keptg[r]) {
                    int    lp = g_srt[base + r];
                    int    gi = g_lidx[base + lp];
                    float4 bx = g_lbox[base + lp];
                    float4* po = (float4*)(out + (size_t)gi * 8);
                    po[0] = make_float4(batch, bx.x, bx.y, bx.z);
                    po[1] = make_float4(bx.w, g_lkey[base + lp], g_lms[base + lp], fcls);
                }
            }
        }
    }
}

extern "C" void kernel_launch(void* const* d_in, const int* in_sizes, int n_in,
                              void* d_out, int out_size) {
    const float* x   = (const float*)d_in[0];
    float*       out = (float*)d_out;

    // 4 boxes per warp, 8 warps per block
    int prep_blocks = (TOT + 31) / 32;
    prep_kernel<<<prep_blocks, 256>>>(x, out);

    // nms with programmatic dependent launch: dispatch overlaps prep's tail,
    // device-side cudaGridDependencySynchronize() provides the data dependency.
    cudaLaunchConfig_t cfg = {};
    cfg.gridDim  = dim3(NCLS, 1, 1);
    cfg.blockDim = dim3(128, 1, 1);
    cfg.dynamicSmemBytes = 0;
    cfg.stream = 0;
    cudaLaunchAttribute attr[1];
    attr[0].id = cudaLaunchAttributeProgrammaticStreamSerialization;
    attr[0].val.programmaticStreamSerializationAllowed = 1;
    cfg.attrs = attr;
    cfg.numAttrs = 1;
    cudaError_t e = cudaLaunchKernelEx(&cfg, nms_out_kernel, out);
    if (e != cudaSuccess) {
        // fallback: plain launch (keeps graph valid if PDL capture unsupported)
        nms_out_kernel<<<NCLS, 128>>>(out);
    }
}